// round 14
// baseline (speedup 1.0000x reference)
#include <cuda_runtime.h>
#include <cuda_bf16.h>
#include <cuda_fp16.h>
#include <cstdint>

#define S_LEN 512
#define BATCH 64
#define D_IN  512
#define H_DIM 1024
#define G4    4096
#define M_ROWS 32768
#define NBLK_R 64                   // recurrence CTAs (each owns 64 gate-cols = 16 h-cols)

// ---- recurrence SMEM layout (bytes) ----
// W: 16 chunks x (64 rows x 144B), single fp16 image = 147456
#define RSM_H     147456            // 3 bufs x 9216 (fp16 h image, 64 rows x 144B)
#define RSM_G     175104            // gates 64x64 f32 = 16384
#define RSM_TOTAL 191488
// ---- gx GEMM SMEM: 3 bufs x 36864 (A, B @ 18432 each) ----
#define GSM_BUF   36864
#define GSM_TOTAL 110592

// ---------------- device scratch ----------------
__device__ float g_bh_p[G4];
__device__ float g_gx[(size_t)M_ROWS * G4];
__device__ __half g_x16[(size_t)M_ROWS * D_IN];         // x fp16
__device__ __half g_Wx16[(size_t)G4 * D_IN];            // Wx fp16, n-major, permuted
__device__ __half g_Wr[(size_t)NBLK_R * 73728];         // per-CTA padded W chunk images (fp16)
__device__ __half g_h[2][BATCH * H_DIM];                // single fp16 h image, ping-pong
__device__ unsigned g_bar_count, g_bar_gen;

// ---------------- helpers ----------------
__device__ __forceinline__ uint32_t smem_u32(const void* p) {
    uint32_t a;
    asm("{ .reg .u64 t; cvta.to.shared.u64 t, %1; cvt.u32.u64 %0, t; }" : "=r"(a) : "l"(p));
    return a;
}
__device__ __forceinline__ void ldm4(uint32_t a, uint32_t& r0, uint32_t& r1, uint32_t& r2, uint32_t& r3) {
    asm volatile("ldmatrix.sync.aligned.m8n8.x4.shared.b16 {%0,%1,%2,%3}, [%4];"
                 : "=r"(r0), "=r"(r1), "=r"(r2), "=r"(r3) : "r"(a));
}
__device__ __forceinline__ void mma_f16(float* c, uint32_t a0, uint32_t a1, uint32_t a2, uint32_t a3,
                                        uint32_t b0, uint32_t b1) {
    asm volatile("mma.sync.aligned.m16n8k16.row.col.f32.f16.f16.f32 "
                 "{%0,%1,%2,%3}, {%4,%5,%6,%7}, {%8,%9}, {%0,%1,%2,%3};"
                 : "+f"(c[0]), "+f"(c[1]), "+f"(c[2]), "+f"(c[3])
                 : "r"(a0), "r"(a1), "r"(a2), "r"(a3), "r"(b0), "r"(b1));
}
__device__ __forceinline__ void cp16(uint32_t dst, const void* src) {
    asm volatile("cp.async.cg.shared.global [%0], [%1], 16;" :: "r"(dst), "l"(src) : "memory");
}
__device__ __forceinline__ void cp_commit() { asm volatile("cp.async.commit_group;" ::: "memory"); }
__device__ __forceinline__ void cp_wait1()  { asm volatile("cp.async.wait_group 1;" ::: "memory"); }
__device__ __forceinline__ void cp_wait0()  { asm volatile("cp.async.wait_group 0;" ::: "memory"); }
__device__ __forceinline__ float sigm(float x) { return 1.0f / (1.0f + __expf(-x)); }

__device__ __forceinline__ void grid_sync(unsigned& bar) {
    __syncthreads();
    if (threadIdx.x == 0) {
        __threadfence();
        unsigned t = atomicAdd(&g_bar_count, 1u);
        bar += 1;
        if (t == gridDim.x - 1u) {
            atomicExch(&g_bar_count, 0u);
            __threadfence();
            atomicAdd(&g_bar_gen, 1u);
        } else {
            while ((int)(atomicAdd(&g_bar_gen, 0u) - bar) < 0) __nanosleep(64);
        }
    }
    __syncthreads();
}

// ---------------- prep: Wx -> n-major permuted fp16; bias ----------------
__global__ void prep_wxb(const float* __restrict__ Wx, const float* __restrict__ bh) {
    int idx = blockIdx.x * blockDim.x + threadIdx.x;      // 4096*512
    if (idx >= G4 * D_IN) return;
    int n = idx >> 9, k = idx & 511;
    float v = Wx[(size_t)k * G4 + (n & 3) * H_DIM + (n >> 2)];
    g_Wx16[idx] = __float2half(v);
    if (k == 0) g_bh_p[n] = bh[(n & 3) * H_DIM + (n >> 2)];
}

// ---------------- prep: x -> fp16 ----------------
__global__ void conv_x(const float* __restrict__ x) {
    size_t idx = (size_t)blockIdx.x * blockDim.x + threadIdx.x;
    if (idx >= (size_t)M_ROWS * D_IN) return;
    g_x16[idx] = __float2half(x[idx]);
}

// ---------------- prep: per-CTA padded W chunk images (single fp16) ----------------
// image: 16 chunks x (64 n-rows x 72 elems [64 data + 8 pad])
__global__ void prep_wrec(const float* __restrict__ Wh) {
    size_t idx = (size_t)blockIdx.x * blockDim.x + threadIdx.x;
    if (idx >= (size_t)NBLK_R * 73728) return;
    int bid = (int)(idx / 73728);
    int e = (int)(idx % 73728);
    int c = e / 4608, rr = e % 4608;
    int n = rr / 72, k = rr % 72;
    __half hi = __float2half(0.f);
    if (k < 64) {
        int cn = bid * 64 + n;
        hi = __float2half(Wh[(size_t)(c * 64 + k) * G4 + (cn & 3) * H_DIM + (cn >> 2)]);
    }
    g_Wr[idx] = hi;
}

// ---------------- gx GEMM (mma.sync fp16 single-term): g_gx = x @ Wx_p ----------------
__global__ __launch_bounds__(512, 1) void gemm_gx() {
    extern __shared__ char smem[];
    const uint32_t sb = smem_u32(smem);
    const int tid = threadIdx.x, lane = tid & 31, w = tid >> 5;
    const int mB = blockIdx.y * 128, nB = blockIdx.x * 128;
    const int m0 = (w & 3) * 32, n0 = (w >> 2) * 32;

    float acc[2][4][4];
#pragma unroll
    for (int a = 0; a < 2; ++a)
#pragma unroll
        for (int b = 0; b < 4; ++b)
#pragma unroll
            for (int d = 0; d < 4; ++d) acc[a][b][d] = 0.f;

    uint32_t aoff[2], boff[2];
#pragma unroll
    for (int mt = 0; mt < 2; ++mt)
        aoff[mt] = (uint32_t)(m0 + mt * 16 + (lane & 15)) * 144u + (uint32_t)(lane >> 4) * 16u;
#pragma unroll
    for (int g = 0; g < 2; ++g)
        boff[g] = (uint32_t)(n0 + g * 16 + ((lane >> 4) << 3) + (lane & 7)) * 144u +
                  (uint32_t)((lane >> 3) & 1) * 16u;

#define GX_ISSUE(ch, buf) do {                                                     \
    _Pragma("unroll")                                                              \
    for (int q = 0; q < 4; ++q) {                                                  \
        int id = tid + q * 512;                                                    \
        int arr = id >> 10, rem = id & 1023, row = rem >> 3, seg = rem & 7;        \
        uint32_t dst = sb + (uint32_t)(buf) * (uint32_t)GSM_BUF +                  \
                       (uint32_t)arr * 18432u +                                    \
                       (uint32_t)row * 144u + (uint32_t)seg * 16u;                 \
        const __half* src;                                                         \
        if (arr == 0) src = g_x16 + (size_t)(mB + row) * 512;                      \
        else          src = g_Wx16 + (size_t)(nB + row) * 512;                     \
        cp16(dst, src + (ch) * 64 + seg * 8);                                      \
    }                                                                              \
    cp_commit();                                                                   \
} while (0)

    GX_ISSUE(0, 0);
    GX_ISSUE(1, 1);
    for (int c = 0; c < 8; ++c) {
        if (c < 7) cp_wait1(); else cp_wait0();
        __syncthreads();
        const uint32_t base = sb + (uint32_t)(c % 3) * (uint32_t)GSM_BUF;
#pragma unroll
        for (int kk = 0; kk < 4; ++kk) {
            const uint32_t o = kk * 32;
            uint32_t av[2][4], bv[2][4];
#pragma unroll
            for (int mt = 0; mt < 2; ++mt)
                ldm4(base + aoff[mt] + o, av[mt][0], av[mt][1], av[mt][2], av[mt][3]);
#pragma unroll
            for (int g = 0; g < 2; ++g)
                ldm4(base + 18432u + boff[g] + o, bv[g][0], bv[g][1], bv[g][2], bv[g][3]);
#pragma unroll
            for (int mt = 0; mt < 2; ++mt)
#pragma unroll
                for (int g = 0; g < 2; ++g) {
                    mma_f16(acc[mt][g * 2],     av[mt][0], av[mt][1], av[mt][2], av[mt][3], bv[g][0], bv[g][1]);
                    mma_f16(acc[mt][g * 2 + 1], av[mt][0], av[mt][1], av[mt][2], av[mt][3], bv[g][2], bv[g][3]);
                }
        }
        __syncthreads();
        if (c < 6) GX_ISSUE(c + 2, (c + 2) % 3);
    }
#undef GX_ISSUE
#pragma unroll
    for (int mt = 0; mt < 2; ++mt)
#pragma unroll
        for (int g = 0; g < 2; ++g)
#pragma unroll
            for (int hf = 0; hf < 2; ++hf) {
                int m = mB + m0 + mt * 16 + (lane >> 2);
                int n = nB + n0 + g * 16 + hf * 8 + (lane & 3) * 2;
                float* f = acc[mt][g * 2 + hf];
                *(float2*)&g_gx[(size_t)m * G4 + n] = make_float2(f[0], f[1]);
                *(float2*)&g_gx[(size_t)(m + 8) * G4 + n] = make_float2(f[2], f[3]);
            }
}

// ---------------- persistent mma.sync recurrence: 64 CTAs, 64 gate-cols each ------
__global__ __launch_bounds__(256, 1) void lstm_rec(const float* __restrict__ h0,
                                                   const float* __restrict__ c0,
                                                   float* __restrict__ out) {
    extern __shared__ char smem[];
    const uint32_t sb = smem_u32(smem);
    const int tid = threadIdx.x, lane = tid & 31, w = tid >> 5, bid = blockIdx.x;
    const int hcb = bid * 16;                 // 16 h-cols per CTA
    const int m0 = (w & 3) * 16;              // 4 m-tiles cover M=64
    const int n0 = (w >> 2) * 32;             // 2 n-groups of 32 cover N=64

    // resident W slice (single fp16): 16 chunks x 64 rows x 144B
    {
        const int4* sw = (const int4*)(g_Wr + (size_t)bid * 73728);
        int4* dw = (int4*)smem;
        for (int i = tid; i < 9216; i += 256) dw[i] = sw[i];
    }
    // h0 -> fp16 ping buffer 0 (disjoint flat slice per CTA)
    for (int i = tid; i < 1024; i += 256) {
        int p = bid * 1024 + i;
        g_h[0][p] = __float2half(h0[p]);
    }
    // per-thread: batch row eb, 4 h-cols (tid&3)*4 + j
    const int eb = tid >> 2, e4 = (tid & 3) * 4;
    float c_r[4];
    float4 bias4[4];
#pragma unroll
    for (int j = 0; j < 4; ++j) {
        c_r[j] = c0[eb * H_DIM + hcb + e4 + j];
        bias4[j] = *(const float4*)&g_bh_p[bid * 64 + e4 * 4 + j * 4];
    }

    const uint32_t a_off = (uint32_t)(m0 + (lane & 15)) * 144u + (uint32_t)(lane >> 4) * 16u;
    uint32_t b_off[2];
#pragma unroll
    for (int g = 0; g < 2; ++g)
        b_off[g] = (uint32_t)(n0 + g * 16 + ((lane >> 4) << 3) + (lane & 7)) * 144u +
                   (uint32_t)((lane >> 3) & 1) * 16u;

    unsigned bar = 0;
    if (tid == 0) bar = atomicAdd(&g_bar_gen, 0u);
    grid_sync(bar);

    for (int t = 0; t < S_LEN; ++t) {
        const int nb = t & 1;
        // prefetch gx (raw, bias added below): 4 float4 per thread
        float4 gv[4];
#pragma unroll
        for (int j = 0; j < 4; ++j)
            gv[j] = *(const float4*)&g_gx[(size_t)(t * BATCH + eb) * G4 + bid * 64 + e4 * 4 + j * 4];

        // 4 independent accumulators (4 n-octets of this warp's N32 group)
        float a0[4] = {0.f, 0.f, 0.f, 0.f};
        float a1[4] = {0.f, 0.f, 0.f, 0.f};
        float a2[4] = {0.f, 0.f, 0.f, 0.f};
        float a3[4] = {0.f, 0.f, 0.f, 0.f};

#define H_ISSUE(ch, buf) do {                                                      \
    _Pragma("unroll")                                                              \
    for (int q = 0; q < 2; ++q) {                                                  \
        int id = tid + q * 256;                                                    \
        int row = id >> 3, seg = id & 7;                                           \
        uint32_t dst = sb + RSM_H + (uint32_t)(buf) * 9216u +                      \
                       (uint32_t)row * 144u + (uint32_t)seg * 16u;                 \
        const __half* src = g_h[nb] + row * H_DIM + (ch) * 64 + seg * 8;           \
        cp16(dst, src);                                                            \
    }                                                                              \
    cp_commit();                                                                   \
} while (0)

        H_ISSUE(0, 0);
        H_ISSUE(1, 1);
        for (int c = 0; c < 16; ++c) {
            if (c < 15) cp_wait1(); else cp_wait0();
            __syncthreads();
            const uint32_t ah = sb + RSM_H + (uint32_t)(c % 3) * 9216u + a_off;
            const uint32_t bh0 = sb + (uint32_t)c * 9216u + b_off[0];
            const uint32_t bh1 = sb + (uint32_t)c * 9216u + b_off[1];
#pragma unroll
            for (int kk = 0; kk < 4; ++kk) {
                const uint32_t o = kk * 32;
                uint32_t A0, A1, A2, A3;
                uint32_t B0, B1, B2, B3, C0, C1, C2, C3;
                ldm4(ah + o, A0, A1, A2, A3);
                ldm4(bh0 + o, B0, B1, B2, B3);
                ldm4(bh1 + o, C0, C1, C2, C3);
                mma_f16(a0, A0, A1, A2, A3, B0, B1);
                mma_f16(a1, A0, A1, A2, A3, B2, B3);
                mma_f16(a2, A0, A1, A2, A3, C0, C1);
                mma_f16(a3, A0, A1, A2, A3, C2, C3);
            }
            if (c < 14) H_ISSUE(c + 2, (c + 2) % 3);
        }
#undef H_ISSUE

        // stage gates (64 x 64 f32)
        {
            float* G = (float*)(smem + RSM_G);
            int r0 = m0 + (lane >> 2), cb0 = n0 + (lane & 3) * 2;
            *(float2*)&G[r0 * 64 + cb0]            = make_float2(a0[0], a0[1]);
            *(float2*)&G[(r0 + 8) * 64 + cb0]      = make_float2(a0[2], a0[3]);
            *(float2*)&G[r0 * 64 + cb0 + 8]        = make_float2(a1[0], a1[1]);
            *(float2*)&G[(r0 + 8) * 64 + cb0 + 8]  = make_float2(a1[2], a1[3]);
            *(float2*)&G[r0 * 64 + cb0 + 16]       = make_float2(a2[0], a2[1]);
            *(float2*)&G[(r0 + 8) * 64 + cb0 + 16] = make_float2(a2[2], a2[3]);
            *(float2*)&G[r0 * 64 + cb0 + 24]       = make_float2(a3[0], a3[1]);
            *(float2*)&G[(r0 + 8) * 64 + cb0 + 24] = make_float2(a3[2], a3[3]);
        }
        __syncthreads();

        // elementwise LSTM: 4 h-cols per thread
        const int nb2 = nb ^ 1;
        const float* G = (const float*)(smem + RSM_G);
        __half hout[4];
#pragma unroll
        for (int j = 0; j < 4; ++j) {
            float4 gr = *(const float4*)&G[eb * 64 + e4 * 4 + j * 4];
            float gi = gr.x + gv[j].x + bias4[j].x;
            float gf = gr.y + gv[j].y + bias4[j].y;
            float gj = gr.z + gv[j].z + bias4[j].z;
            float go = gr.w + gv[j].w + bias4[j].w;
            float cn = c_r[j] * sigm(gf + 1.0f) + sigm(gi) * tanhf(gj);
            c_r[j] = cn;
            float hn = tanhf(cn) * sigm(go);
            hout[j] = __float2half(hn);
            if (t == S_LEN - 1) {
                out[eb * H_DIM + hcb + e4 + j] = hn;
                out[BATCH * H_DIM + eb * H_DIM + hcb + e4 + j] = cn;
            }
        }
        *(uint2*)&g_h[nb2][eb * H_DIM + hcb + e4] = *(uint2*)hout;
        grid_sync(bar);
    }
}

// ---------------- host launch ----------------
extern "C" void kernel_launch(void* const* d_in, const int* in_sizes, int n_in,
                              void* d_out, int out_size) {
    const float* x  = (const float*)d_in[0];
    const float* h0 = (const float*)d_in[1];
    const float* c0 = (const float*)d_in[2];
    const float* Wx = (const float*)d_in[3];
    const float* Wh = (const float*)d_in[4];
    const float* bh = (const float*)d_in[5];
    float* out = (float*)d_out;

    prep_wxb<<<(G4 * D_IN + 255) / 256, 256>>>(Wx, bh);
    conv_x<<<(M_ROWS * D_IN + 511) / 512, 512>>>(x);
    prep_wrec<<<(NBLK_R * 73728 + 255) / 256, 256>>>(Wh);
    cudaFuncSetAttribute(gemm_gx, cudaFuncAttributeMaxDynamicSharedMemorySize, GSM_TOTAL);
    gemm_gx<<<dim3(G4 / 128, M_ROWS / 128), 512, GSM_TOTAL>>>();
    cudaFuncSetAttribute(lstm_rec, cudaFuncAttributeMaxDynamicSharedMemorySize, RSM_TOTAL);
    lstm_rec<<<NBLK_R, 256, RSM_TOTAL>>>(h0, c0, out);
}

// round 15
// speedup vs baseline: 1.1967x; 1.1967x over previous
#include <cuda_runtime.h>
#include <cuda_bf16.h>
#include <cuda_fp16.h>
#include <cstdint>

#define S_LEN 512
#define BATCH 64
#define D_IN  512
#define H_DIM 1024
#define G4    4096
#define M_ROWS 32768
#define NBLK  128

// ---- recurrence SMEM layout (bytes) ----
// W: 16 chunks x (32 rows x 144B), single fp16 image @ [0, 73728)
#define RSM_H     73728             // 4 bufs x 9216 (single fp16 h image)
#define RSM_G     110592            // gates 64x32 f32
#define RSM_TOTAL 118784
// ---- gx GEMM SMEM: 3 bufs x 36864 (A, B @ 18432 each) ----
#define GSM_BUF   36864
#define GSM_TOTAL 110592

// ---------------- device scratch ----------------
__device__ float g_bh_p[G4];
__device__ float g_gx[(size_t)M_ROWS * G4];
__device__ __half g_x16[(size_t)M_ROWS * D_IN];         // x fp16
__device__ __half g_Wx16[(size_t)G4 * D_IN];            // Wx fp16, n-major, permuted
__device__ __half g_Wr[(size_t)NBLK * 36864];           // per-CTA padded W chunk images (fp16)
__device__ __half g_h[2][BATCH * H_DIM];                // single fp16 h image, ping-pong
__device__ unsigned g_bar_count, g_bar_gen;

// ---------------- helpers ----------------
__device__ __forceinline__ uint32_t smem_u32(const void* p) {
    uint32_t a;
    asm("{ .reg .u64 t; cvta.to.shared.u64 t, %1; cvt.u32.u64 %0, t; }" : "=r"(a) : "l"(p));
    return a;
}
__device__ __forceinline__ void ldm4(uint32_t a, uint32_t& r0, uint32_t& r1, uint32_t& r2, uint32_t& r3) {
    asm volatile("ldmatrix.sync.aligned.m8n8.x4.shared.b16 {%0,%1,%2,%3}, [%4];"
                 : "=r"(r0), "=r"(r1), "=r"(r2), "=r"(r3) : "r"(a));
}
__device__ __forceinline__ void mma_f16(float* c, uint32_t a0, uint32_t a1, uint32_t a2, uint32_t a3,
                                        uint32_t b0, uint32_t b1) {
    asm volatile("mma.sync.aligned.m16n8k16.row.col.f32.f16.f16.f32 "
                 "{%0,%1,%2,%3}, {%4,%5,%6,%7}, {%8,%9}, {%0,%1,%2,%3};"
                 : "+f"(c[0]), "+f"(c[1]), "+f"(c[2]), "+f"(c[3])
                 : "r"(a0), "r"(a1), "r"(a2), "r"(a3), "r"(b0), "r"(b1));
}
__device__ __forceinline__ void cp16(uint32_t dst, const void* src) {
    asm volatile("cp.async.cg.shared.global [%0], [%1], 16;" :: "r"(dst), "l"(src) : "memory");
}
__device__ __forceinline__ void cp_commit() { asm volatile("cp.async.commit_group;" ::: "memory"); }
__device__ __forceinline__ void cp_wait2()  { asm volatile("cp.async.wait_group 2;" ::: "memory"); }
__device__ __forceinline__ void cp_wait1()  { asm volatile("cp.async.wait_group 1;" ::: "memory"); }
__device__ __forceinline__ void cp_wait0()  { asm volatile("cp.async.wait_group 0;" ::: "memory"); }
__device__ __forceinline__ float sigm(float x) { return 1.0f / (1.0f + __expf(-x)); }

__device__ __forceinline__ void grid_sync(unsigned& bar) {
    __syncthreads();
    if (threadIdx.x == 0) {
        __threadfence();
        unsigned t = atomicAdd(&g_bar_count, 1u);
        bar += 1;
        if (t == gridDim.x - 1u) {
            atomicExch(&g_bar_count, 0u);
            __threadfence();
            atomicAdd(&g_bar_gen, 1u);
        } else {
            while ((int)(atomicAdd(&g_bar_gen, 0u) - bar) < 0) __nanosleep(64);
        }
    }
    __syncthreads();
}

// ---------------- prep: Wx -> n-major permuted fp16; bias ----------------
__global__ void prep_wxb(const float* __restrict__ Wx, const float* __restrict__ bh) {
    int idx = blockIdx.x * blockDim.x + threadIdx.x;      // 4096*512
    if (idx >= G4 * D_IN) return;
    int n = idx >> 9, k = idx & 511;
    float v = Wx[(size_t)k * G4 + (n & 3) * H_DIM + (n >> 2)];
    g_Wx16[idx] = __float2half(v);
    if (k == 0) g_bh_p[n] = bh[(n & 3) * H_DIM + (n >> 2)];
}

// ---------------- prep: x -> fp16 ----------------
__global__ void conv_x(const float* __restrict__ x) {
    size_t idx = (size_t)blockIdx.x * blockDim.x + threadIdx.x;
    if (idx >= (size_t)M_ROWS * D_IN) return;
    g_x16[idx] = __float2half(x[idx]);
}

// ---------------- prep: per-CTA padded W chunk images (single fp16) ----------------
// image: 16 chunks x (32 n-rows x 72 elems [64 data + 8 pad])
__global__ void prep_wrec(const float* __restrict__ Wh) {
    size_t idx = (size_t)blockIdx.x * blockDim.x + threadIdx.x;
    if (idx >= (size_t)NBLK * 36864) return;
    int bid = (int)(idx / 36864);
    int e = (int)(idx % 36864);
    int c = e / 2304, rr = e % 2304;
    int n = rr / 72, k = rr % 72;
    __half hi = __float2half(0.f);
    if (k < 64) {
        int cn = bid * 32 + n;
        hi = __float2half(Wh[(size_t)(c * 64 + k) * G4 + (cn & 3) * H_DIM + (cn >> 2)]);
    }
    g_Wr[idx] = hi;
}

// ---------------- gx GEMM (mma.sync fp16 single-term): g_gx = x @ Wx_p ----------------
__global__ __launch_bounds__(512, 1) void gemm_gx() {
    extern __shared__ char smem[];
    const uint32_t sb = smem_u32(smem);
    const int tid = threadIdx.x, lane = tid & 31, w = tid >> 5;
    const int mB = blockIdx.y * 128, nB = blockIdx.x * 128;
    const int m0 = (w & 3) * 32, n0 = (w >> 2) * 32;

    float acc[2][4][4];
#pragma unroll
    for (int a = 0; a < 2; ++a)
#pragma unroll
        for (int b = 0; b < 4; ++b)
#pragma unroll
            for (int d = 0; d < 4; ++d) acc[a][b][d] = 0.f;

    uint32_t aoff[2], boff[2];
#pragma unroll
    for (int mt = 0; mt < 2; ++mt)
        aoff[mt] = (uint32_t)(m0 + mt * 16 + (lane & 15)) * 144u + (uint32_t)(lane >> 4) * 16u;
#pragma unroll
    for (int g = 0; g < 2; ++g)
        boff[g] = (uint32_t)(n0 + g * 16 + ((lane >> 4) << 3) + (lane & 7)) * 144u +
                  (uint32_t)((lane >> 3) & 1) * 16u;

#define GX_ISSUE(ch, buf) do {                                                     \
    _Pragma("unroll")                                                              \
    for (int q = 0; q < 4; ++q) {                                                  \
        int id = tid + q * 512;                                                    \
        int arr = id >> 10, rem = id & 1023, row = rem >> 3, seg = rem & 7;        \
        uint32_t dst = sb + (uint32_t)(buf) * (uint32_t)GSM_BUF +                  \
                       (uint32_t)arr * 18432u +                                    \
                       (uint32_t)row * 144u + (uint32_t)seg * 16u;                 \
        const __half* src;                                                         \
        if (arr == 0) src = g_x16 + (size_t)(mB + row) * 512;                      \
        else          src = g_Wx16 + (size_t)(nB + row) * 512;                     \
        cp16(dst, src + (ch) * 64 + seg * 8);                                      \
    }                                                                              \
    cp_commit();                                                                   \
} while (0)

    GX_ISSUE(0, 0);
    GX_ISSUE(1, 1);
    for (int c = 0; c < 8; ++c) {
        if (c < 7) cp_wait1(); else cp_wait0();
        __syncthreads();
        const uint32_t base = sb + (uint32_t)(c % 3) * (uint32_t)GSM_BUF;
#pragma unroll
        for (int kk = 0; kk < 4; ++kk) {
            const uint32_t o = kk * 32;
            uint32_t av[2][4], bv[2][4];
#pragma unroll
            for (int mt = 0; mt < 2; ++mt)
                ldm4(base + aoff[mt] + o, av[mt][0], av[mt][1], av[mt][2], av[mt][3]);
#pragma unroll
            for (int g = 0; g < 2; ++g)
                ldm4(base + 18432u + boff[g] + o, bv[g][0], bv[g][1], bv[g][2], bv[g][3]);
#pragma unroll
            for (int mt = 0; mt < 2; ++mt)
#pragma unroll
                for (int g = 0; g < 2; ++g) {
                    mma_f16(acc[mt][g * 2],     av[mt][0], av[mt][1], av[mt][2], av[mt][3], bv[g][0], bv[g][1]);
                    mma_f16(acc[mt][g * 2 + 1], av[mt][0], av[mt][1], av[mt][2], av[mt][3], bv[g][2], bv[g][3]);
                }
        }
        __syncthreads();
        if (c < 6) GX_ISSUE(c + 2, (c + 2) % 3);
    }
#undef GX_ISSUE
#pragma unroll
    for (int mt = 0; mt < 2; ++mt)
#pragma unroll
        for (int g = 0; g < 2; ++g)
#pragma unroll
            for (int hf = 0; hf < 2; ++hf) {
                int m = mB + m0 + mt * 16 + (lane >> 2);
                int n = nB + n0 + g * 16 + hf * 8 + (lane & 3) * 2;
                float* f = acc[mt][g * 2 + hf];
                *(float2*)&g_gx[(size_t)m * G4 + n] = make_float2(f[0], f[1]);
                *(float2*)&g_gx[(size_t)(m + 8) * G4 + n] = make_float2(f[2], f[3]);
            }
}

// ---------------- persistent mma.sync recurrence (fp16 single-W, depth-3 prefetch) ----
__global__ __launch_bounds__(256, 1) void lstm_rec(const float* __restrict__ h0,
                                                   const float* __restrict__ c0,
                                                   float* __restrict__ out) {
    extern __shared__ char smem[];
    const uint32_t sb = smem_u32(smem);
    const int tid = threadIdx.x, lane = tid & 31, w = tid >> 5, bid = blockIdx.x;
    const int hcb = bid * 8;
    const int m0 = (w & 3) * 16, n0 = (w >> 2) * 16;

    // resident W slice (single fp16)
    {
        const int4* sw = (const int4*)(g_Wr + (size_t)bid * 36864);
        int4* dw = (int4*)smem;
        for (int i = tid; i < 4608; i += 256) dw[i] = sw[i];
    }
    // h0 -> fp16 ping buffer 0 (disjoint slice per CTA)
    for (int i = tid; i < 512; i += 256) {
        int p = bid * 512 + i;
        g_h[0][p] = __float2half(h0[p]);
    }
    // per-thread cell state + bias
    const int eb = tid >> 3, ehl = tid & 7;
    float c_r[2];
    c_r[0] = c0[eb * H_DIM + hcb + ehl];
    c_r[1] = c0[(eb + 32) * H_DIM + hcb + ehl];
    const float4 br = *(const float4*)&g_bh_p[bid * 32 + ehl * 4];

    const uint32_t a_off = (uint32_t)(m0 + (lane & 15)) * 144u + (uint32_t)(lane >> 4) * 16u;
    const uint32_t b_off = (uint32_t)(n0 + ((lane >> 4) << 3) + (lane & 7)) * 144u +
                           (uint32_t)((lane >> 3) & 1) * 16u;

    unsigned bar = 0;
    if (tid == 0) bar = atomicAdd(&g_bar_gen, 0u);
    grid_sync(bar);

    for (int t = 0; t < S_LEN; ++t) {
        const int nb = t & 1;
        // prefetch gx (raw, bias added below)
        float4 gv0 = *(const float4*)&g_gx[(size_t)(t * BATCH + eb) * G4 + bid * 32 + ehl * 4];
        float4 gv1 = *(const float4*)&g_gx[(size_t)(t * BATCH + eb + 32) * G4 + bid * 32 + ehl * 4];

        // 2 independent accumulators (n-halves)
        float a0[4] = {0.f, 0.f, 0.f, 0.f};
        float a1[4] = {0.f, 0.f, 0.f, 0.f};

#define H_ISSUE(ch, buf) do {                                                      \
    _Pragma("unroll")                                                              \
    for (int q = 0; q < 2; ++q) {                                                  \
        int id = tid + q * 256;                                                    \
        int row = id >> 3, seg = id & 7;                                           \
        uint32_t dst = sb + RSM_H + (uint32_t)(buf) * 9216u +                      \
                       (uint32_t)row * 144u + (uint32_t)seg * 16u;                 \
        const __half* src = g_h[nb] + row * H_DIM + (ch) * 64 + seg * 8;           \
        cp16(dst, src);                                                            \
    }                                                                              \
    cp_commit();                                                                   \
} while (0)

        H_ISSUE(0, 0);
        H_ISSUE(1, 1);
        H_ISSUE(2, 2);
        for (int c = 0; c < 16; ++c) {
            if (c < 14) cp_wait2(); else if (c == 14) cp_wait1(); else cp_wait0();
            __syncthreads();
            const uint32_t ah = sb + RSM_H + (uint32_t)(c & 3) * 9216u + a_off;
            const uint32_t bh = sb + (uint32_t)c * 4608u + b_off;
#pragma unroll
            for (int kk = 0; kk < 4; ++kk) {
                const uint32_t o = kk * 32;
                uint32_t A0, A1, A2, A3;
                uint32_t B0, B1, B2, B3;
                ldm4(ah + o, A0, A1, A2, A3);
                ldm4(bh + o, B0, B1, B2, B3);
                mma_f16(a0, A0, A1, A2, A3, B0, B1);
                mma_f16(a1, A0, A1, A2, A3, B2, B3);
            }
            if (c < 13) H_ISSUE(c + 3, (c + 3) & 3);   // buf (c-1)&3: freed by this chunk's sync
        }
#undef H_ISSUE

        // stage gates
        {
            float* G = (float*)(smem + RSM_G);
            int r0 = m0 + (lane >> 2), cb0 = n0 + (lane & 3) * 2;
            *(float2*)&G[r0 * 32 + cb0]           = make_float2(a0[0], a0[1]);
            *(float2*)&G[(r0 + 8) * 32 + cb0]     = make_float2(a0[2], a0[3]);
            *(float2*)&G[r0 * 32 + cb0 + 8]       = make_float2(a1[0], a1[1]);
            *(float2*)&G[(r0 + 8) * 32 + cb0 + 8] = make_float2(a1[2], a1[3]);
        }
        __syncthreads();

        // elementwise LSTM for (eb, ehl) and (eb+32, ehl)
        const int nb2 = nb ^ 1;
        const float* G = (const float*)(smem + RSM_G);
#pragma unroll
        for (int q = 0; q < 2; ++q) {
            int b = eb + q * 32;
            float4 gr = *(const float4*)&G[b * 32 + ehl * 4];
            float4 gx = q ? gv1 : gv0;
            float gi = gr.x + gx.x + br.x;
            float gf = gr.y + gx.y + br.y;
            float gj = gr.z + gx.z + br.z;
            float go = gr.w + gx.w + br.w;
            float cn = c_r[q] * sigm(gf + 1.0f) + sigm(gi) * tanhf(gj);
            c_r[q] = cn;
            float hn = tanhf(cn) * sigm(go);
            g_h[nb2][b * H_DIM + hcb + ehl] = __float2half(hn);
            if (t == S_LEN - 1) {
                out[b * H_DIM + hcb + ehl] = hn;
                out[BATCH * H_DIM + b * H_DIM + hcb + ehl] = cn;
            }
        }
        grid_sync(bar);
    }
}

// ---------------- host launch ----------------
extern "C" void kernel_launch(void* const* d_in, const int* in_sizes, int n_in,
                              void* d_out, int out_size) {
    const float* x  = (const float*)d_in[0];
    const float* h0 = (const float*)d_in[1];
    const float* c0 = (const float*)d_in[2];
    const float* Wx = (const float*)d_in[3];
    const float* Wh = (const float*)d_in[4];
    const float* bh = (const float*)d_in[5];
    float* out = (float*)d_out;

    prep_wxb<<<(G4 * D_IN + 255) / 256, 256>>>(Wx, bh);
    conv_x<<<(M_ROWS * D_IN + 511) / 512, 512>>>(x);
    prep_wrec<<<(NBLK * 36864 + 255) / 256, 256>>>(Wh);
    cudaFuncSetAttribute(gemm_gx, cudaFuncAttributeMaxDynamicSharedMemorySize, GSM_TOTAL);
    gemm_gx<<<dim3(G4 / 128, M_ROWS / 128), 512, GSM_TOTAL>>>();
    cudaFuncSetAttribute(lstm_rec, cudaFuncAttributeMaxDynamicSharedMemorySize, RSM_TOTAL);
    lstm_rec<<<NBLK, 256, RSM_TOTAL>>>(h0, c0, out);
}

// round 16
// speedup vs baseline: 1.2623x; 1.0548x over previous
#include <cuda_runtime.h>
#include <cuda_bf16.h>
#include <cuda_fp16.h>
#include <cstdint>

#define S_LEN 512
#define BATCH 64
#define D_IN  512
#define H_DIM 1024
#define G4    4096
#define M_ROWS 32768
#define NBLK  128

// ---- recurrence SMEM layout (bytes) ----
// W: 16 chunks x (32 rows x 144B), single fp16 image @ [0, 73728)
#define RSM_H     73728             // 6 bufs x 9216 (single fp16 h image)
#define RSM_G     129024            // gates 64x32 f32
#define RSM_TOTAL 137216
// ---- gx GEMM SMEM: 4 bufs x 36864 (A, B @ 18432 each) ----
#define GSM_BUF   36864
#define GSM_TOTAL 147456

// ---------------- device scratch ----------------
__device__ float g_bh_p[G4];
__device__ float g_gx[(size_t)M_ROWS * G4];
__device__ __half g_x16[(size_t)M_ROWS * D_IN];         // x fp16
__device__ __half g_Wx16[(size_t)G4 * D_IN];            // Wx fp16, n-major, permuted
__device__ __half g_Wr[(size_t)NBLK * 36864];           // per-CTA padded W chunk images (fp16)
__device__ __half g_h[2][BATCH * H_DIM];                // single fp16 h image, ping-pong
__device__ unsigned g_bar_count, g_bar_gen;

// ---------------- helpers ----------------
__device__ __forceinline__ uint32_t smem_u32(const void* p) {
    uint32_t a;
    asm("{ .reg .u64 t; cvta.to.shared.u64 t, %1; cvt.u32.u64 %0, t; }" : "=r"(a) : "l"(p));
    return a;
}
__device__ __forceinline__ void ldm4(uint32_t a, uint32_t& r0, uint32_t& r1, uint32_t& r2, uint32_t& r3) {
    asm volatile("ldmatrix.sync.aligned.m8n8.x4.shared.b16 {%0,%1,%2,%3}, [%4];"
                 : "=r"(r0), "=r"(r1), "=r"(r2), "=r"(r3) : "r"(a));
}
__device__ __forceinline__ void mma_f16(float* c, uint32_t a0, uint32_t a1, uint32_t a2, uint32_t a3,
                                        uint32_t b0, uint32_t b1) {
    asm volatile("mma.sync.aligned.m16n8k16.row.col.f32.f16.f16.f32 "
                 "{%0,%1,%2,%3}, {%4,%5,%6,%7}, {%8,%9}, {%0,%1,%2,%3};"
                 : "+f"(c[0]), "+f"(c[1]), "+f"(c[2]), "+f"(c[3])
                 : "r"(a0), "r"(a1), "r"(a2), "r"(a3), "r"(b0), "r"(b1));
}
__device__ __forceinline__ void cp16(uint32_t dst, const void* src) {
    asm volatile("cp.async.cg.shared.global [%0], [%1], 16;" :: "r"(dst), "l"(src) : "memory");
}
__device__ __forceinline__ void cp_commit() { asm volatile("cp.async.commit_group;" ::: "memory"); }
__device__ __forceinline__ void cp_waitn(int n) {
    switch (n) {
        case 0: asm volatile("cp.async.wait_group 0;" ::: "memory"); break;
        case 1: asm volatile("cp.async.wait_group 1;" ::: "memory"); break;
        case 2: asm volatile("cp.async.wait_group 2;" ::: "memory"); break;
        case 3: asm volatile("cp.async.wait_group 3;" ::: "memory"); break;
        default: asm volatile("cp.async.wait_group 4;" ::: "memory"); break;
    }
}
__device__ __forceinline__ float sigm(float x) { return 1.0f / (1.0f + __expf(-x)); }

__device__ __forceinline__ void grid_sync(unsigned& bar) {
    __syncthreads();
    if (threadIdx.x == 0) {
        __threadfence();
        unsigned t = atomicAdd(&g_bar_count, 1u);
        bar += 1;
        if (t == gridDim.x - 1u) {
            atomicExch(&g_bar_count, 0u);
            __threadfence();
            atomicAdd(&g_bar_gen, 1u);
        } else {
            while ((int)(atomicAdd(&g_bar_gen, 0u) - bar) < 0) __nanosleep(64);
        }
    }
    __syncthreads();
}

// ---------------- prep: Wx -> n-major permuted fp16; bias ----------------
__global__ void prep_wxb(const float* __restrict__ Wx, const float* __restrict__ bh) {
    int idx = blockIdx.x * blockDim.x + threadIdx.x;      // 4096*512
    if (idx >= G4 * D_IN) return;
    int n = idx >> 9, k = idx & 511;
    float v = Wx[(size_t)k * G4 + (n & 3) * H_DIM + (n >> 2)];
    g_Wx16[idx] = __float2half(v);
    if (k == 0) g_bh_p[n] = bh[(n & 3) * H_DIM + (n >> 2)];
}

// ---------------- prep: x -> fp16 ----------------
__global__ void conv_x(const float* __restrict__ x) {
    size_t idx = (size_t)blockIdx.x * blockDim.x + threadIdx.x;
    if (idx >= (size_t)M_ROWS * D_IN) return;
    g_x16[idx] = __float2half(x[idx]);
}

// ---------------- prep: per-CTA padded W chunk images (single fp16) ----------------
// image: 16 chunks x (32 n-rows x 72 elems [64 data + 8 pad])
__global__ void prep_wrec(const float* __restrict__ Wh) {
    size_t idx = (size_t)blockIdx.x * blockDim.x + threadIdx.x;
    if (idx >= (size_t)NBLK * 36864) return;
    int bid = (int)(idx / 36864);
    int e = (int)(idx % 36864);
    int c = e / 2304, rr = e % 2304;
    int n = rr / 72, k = rr % 72;
    __half hi = __float2half(0.f);
    if (k < 64) {
        int cn = bid * 32 + n;
        hi = __float2half(Wh[(size_t)(c * 64 + k) * G4 + (cn & 3) * H_DIM + (cn >> 2)]);
    }
    g_Wr[idx] = hi;
}

// ---------------- gx GEMM (mma.sync fp16, depth-3 prefetch): g_gx = x @ Wx_p ------
__global__ __launch_bounds__(512, 1) void gemm_gx() {
    extern __shared__ char smem[];
    const uint32_t sb = smem_u32(smem);
    const int tid = threadIdx.x, lane = tid & 31, w = tid >> 5;
    const int mB = blockIdx.y * 128, nB = blockIdx.x * 128;
    const int m0 = (w & 3) * 32, n0 = (w >> 2) * 32;

    float acc[2][4][4];
#pragma unroll
    for (int a = 0; a < 2; ++a)
#pragma unroll
        for (int b = 0; b < 4; ++b)
#pragma unroll
            for (int d = 0; d < 4; ++d) acc[a][b][d] = 0.f;

    uint32_t aoff[2], boff[2];
#pragma unroll
    for (int mt = 0; mt < 2; ++mt)
        aoff[mt] = (uint32_t)(m0 + mt * 16 + (lane & 15)) * 144u + (uint32_t)(lane >> 4) * 16u;
#pragma unroll
    for (int g = 0; g < 2; ++g)
        boff[g] = (uint32_t)(n0 + g * 16 + ((lane >> 4) << 3) + (lane & 7)) * 144u +
                  (uint32_t)((lane >> 3) & 1) * 16u;

#define GX_ISSUE(ch, buf) do {                                                     \
    _Pragma("unroll")                                                              \
    for (int q = 0; q < 4; ++q) {                                                  \
        int id = tid + q * 512;                                                    \
        int arr = id >> 10, rem = id & 1023, row = rem >> 3, seg = rem & 7;        \
        uint32_t dst = sb + (uint32_t)(buf) * (uint32_t)GSM_BUF +                  \
                       (uint32_t)arr * 18432u +                                    \
                       (uint32_t)row * 144u + (uint32_t)seg * 16u;                 \
        const __half* src;                                                         \
        if (arr == 0) src = g_x16 + (size_t)(mB + row) * 512;                      \
        else          src = g_Wx16 + (size_t)(nB + row) * 512;                     \
        cp16(dst, src + (ch) * 64 + seg * 8);                                      \
    }                                                                              \
    cp_commit();                                                                   \
} while (0)

    GX_ISSUE(0, 0);
    GX_ISSUE(1, 1);
    GX_ISSUE(2, 2);
    for (int c = 0; c < 8; ++c) {
        cp_waitn(7 - c < 2 ? 7 - c : 2);
        __syncthreads();
        const uint32_t base = sb + (uint32_t)(c & 3) * (uint32_t)GSM_BUF;
#pragma unroll
        for (int kk = 0; kk < 4; ++kk) {
            const uint32_t o = kk * 32;
            uint32_t av[2][4], bv[2][4];
#pragma unroll
            for (int mt = 0; mt < 2; ++mt)
                ldm4(base + aoff[mt] + o, av[mt][0], av[mt][1], av[mt][2], av[mt][3]);
#pragma unroll
            for (int g = 0; g < 2; ++g)
                ldm4(base + 18432u + boff[g] + o, bv[g][0], bv[g][1], bv[g][2], bv[g][3]);
#pragma unroll
            for (int mt = 0; mt < 2; ++mt)
#pragma unroll
                for (int g = 0; g < 2; ++g) {
                    mma_f16(acc[mt][g * 2],     av[mt][0], av[mt][1], av[mt][2], av[mt][3], bv[g][0], bv[g][1]);
                    mma_f16(acc[mt][g * 2 + 1], av[mt][0], av[mt][1], av[mt][2], av[mt][3], bv[g][2], bv[g][3]);
                }
        }
        __syncthreads();
        if (c < 5) GX_ISSUE(c + 3, (c + 3) & 3);   // buf (c-1)&3: freed by this chunk's sync
    }
#undef GX_ISSUE
#pragma unroll
    for (int mt = 0; mt < 2; ++mt)
#pragma unroll
        for (int g = 0; g < 2; ++g)
#pragma unroll
            for (int hf = 0; hf < 2; ++hf) {
                int m = mB + m0 + mt * 16 + (lane >> 2);
                int n = nB + n0 + g * 16 + hf * 8 + (lane & 3) * 2;
                float* f = acc[mt][g * 2 + hf];
                *(float2*)&g_gx[(size_t)m * G4 + n] = make_float2(f[0], f[1]);
                *(float2*)&g_gx[(size_t)(m + 8) * G4 + n] = make_float2(f[2], f[3]);
            }
}

// ---------------- persistent mma.sync recurrence (fp16 single-W, depth-5 prefetch) ----
__global__ __launch_bounds__(256, 1) void lstm_rec(const float* __restrict__ h0,
                                                   const float* __restrict__ c0,
                                                   float* __restrict__ out) {
    extern __shared__ char smem[];
    const uint32_t sb = smem_u32(smem);
    const int tid = threadIdx.x, lane = tid & 31, w = tid >> 5, bid = blockIdx.x;
    const int hcb = bid * 8;
    const int m0 = (w & 3) * 16, n0 = (w >> 2) * 16;

    // resident W slice (single fp16)
    {
        const int4* sw = (const int4*)(g_Wr + (size_t)bid * 36864);
        int4* dw = (int4*)smem;
        for (int i = tid; i < 4608; i += 256) dw[i] = sw[i];
    }
    // h0 -> fp16 ping buffer 0 (disjoint slice per CTA)
    for (int i = tid; i < 512; i += 256) {
        int p = bid * 512 + i;
        g_h[0][p] = __float2half(h0[p]);
    }
    // per-thread cell state + bias
    const int eb = tid >> 3, ehl = tid & 7;
    float c_r[2];
    c_r[0] = c0[eb * H_DIM + hcb + ehl];
    c_r[1] = c0[(eb + 32) * H_DIM + hcb + ehl];
    const float4 br = *(const float4*)&g_bh_p[bid * 32 + ehl * 4];

    const uint32_t a_off = (uint32_t)(m0 + (lane & 15)) * 144u + (uint32_t)(lane >> 4) * 16u;
    const uint32_t b_off = (uint32_t)(n0 + ((lane >> 4) << 3) + (lane & 7)) * 144u +
                           (uint32_t)((lane >> 3) & 1) * 16u;

    unsigned bar = 0;
    if (tid == 0) bar = atomicAdd(&g_bar_gen, 0u);
    grid_sync(bar);

    for (int t = 0; t < S_LEN; ++t) {
        const int nb = t & 1;
        // prefetch gx (raw, bias added below)
        float4 gv0 = *(const float4*)&g_gx[(size_t)(t * BATCH + eb) * G4 + bid * 32 + ehl * 4];
        float4 gv1 = *(const float4*)&g_gx[(size_t)(t * BATCH + eb + 32) * G4 + bid * 32 + ehl * 4];

        // 2 independent accumulators (n-halves)
        float a0[4] = {0.f, 0.f, 0.f, 0.f};
        float a1[4] = {0.f, 0.f, 0.f, 0.f};

#define H_ISSUE(ch, buf) do {                                                      \
    _Pragma("unroll")                                                              \
    for (int q = 0; q < 2; ++q) {                                                  \
        int id = tid + q * 256;                                                    \
        int row = id >> 3, seg = id & 7;                                           \
        uint32_t dst = sb + RSM_H + (uint32_t)(buf) * 9216u +                      \
                       (uint32_t)row * 144u + (uint32_t)seg * 16u;                 \
        const __half* src = g_h[nb] + row * H_DIM + (ch) * 64 + seg * 8;           \
        cp16(dst, src);                                                            \
    }                                                                              \
    cp_commit();                                                                   \
} while (0)

        H_ISSUE(0, 0);
        H_ISSUE(1, 1);
        H_ISSUE(2, 2);
        H_ISSUE(3, 3);
        H_ISSUE(4, 4);
        for (int c = 0; c < 16; ++c) {
            cp_waitn(15 - c < 4 ? 15 - c : 4);
            __syncthreads();
            const uint32_t ah = sb + RSM_H + (uint32_t)(c % 6) * 9216u + a_off;
            const uint32_t bh = sb + (uint32_t)c * 4608u + b_off;
#pragma unroll
            for (int kk = 0; kk < 4; ++kk) {
                const uint32_t o = kk * 32;
                uint32_t A0, A1, A2, A3;
                uint32_t B0, B1, B2, B3;
                ldm4(ah + o, A0, A1, A2, A3);
                ldm4(bh + o, B0, B1, B2, B3);
                mma_f16(a0, A0, A1, A2, A3, B0, B1);
                mma_f16(a1, A0, A1, A2, A3, B2, B3);
            }
            if (c < 11) H_ISSUE(c + 5, (c + 5) % 6);   // buf (c-1)%6: freed by this chunk's sync
        }
#undef H_ISSUE

        // stage gates
        {
            float* G = (float*)(smem + RSM_G);
            int r0 = m0 + (lane >> 2), cb0 = n0 + (lane & 3) * 2;
            *(float2*)&G[r0 * 32 + cb0]           = make_float2(a0[0], a0[1]);
            *(float2*)&G[(r0 + 8) * 32 + cb0]     = make_float2(a0[2], a0[3]);
            *(float2*)&G[r0 * 32 + cb0 + 8]       = make_float2(a1[0], a1[1]);
            *(float2*)&G[(r0 + 8) * 32 + cb0 + 8] = make_float2(a1[2], a1[3]);
        }
        __syncthreads();

        // elementwise LSTM for (eb, ehl) and (eb+32, ehl)
        const int nb2 = nb ^ 1;
        const float* G = (const float*)(smem + RSM_G);
#pragma unroll
        for (int q = 0; q < 2; ++q) {
            int b = eb + q * 32;
            float4 gr = *(const float4*)&G[b * 32 + ehl * 4];
            float4 gx = q ? gv1 : gv0;
            float gi = gr.x + gx.x + br.x;
            float gf = gr.y + gx.y + br.y;
            float gj = gr.z + gx.z + br.z;
            float go = gr.w + gx.w + br.w;
            float cn = c_r[q] * sigm(gf + 1.0f) + sigm(gi) * tanhf(gj);
            c_r[q] = cn;
            float hn = tanhf(cn) * sigm(go);
            g_h[nb2][b * H_DIM + hcb + ehl] = __float2half(hn);
            if (t == S_LEN - 1) {
                out[b * H_DIM + hcb + ehl] = hn;
                out[BATCH * H_DIM + b * H_DIM + hcb + ehl] = cn;
            }
        }
        grid_sync(bar);
    }
}

// ---------------- host launch ----------------
extern "C" void kernel_launch(void* const* d_in, const int* in_sizes, int n_in,
                              void* d_out, int out_size) {
    const float* x  = (const float*)d_in[0];
    const float* h0 = (const float*)d_in[1];
    const float* c0 = (const float*)d_in[2];
    const float* Wx = (const float*)d_in[3];
    const float* Wh = (const float*)d_in[4];
    const float* bh = (const float*)d_in[5];
    float* out = (float*)d_out;

    prep_wxb<<<(G4 * D_IN + 255) / 256, 256>>>(Wx, bh);
    conv_x<<<(M_ROWS * D_IN + 511) / 512, 512>>>(x);
    prep_wrec<<<(NBLK * 36864 + 255) / 256, 256>>>(Wh);
    cudaFuncSetAttribute(gemm_gx, cudaFuncAttributeMaxDynamicSharedMemorySize, GSM_TOTAL);
    gemm_gx<<<dim3(G4 / 128, M_ROWS / 128), 512, GSM_TOTAL>>>();
    cudaFuncSetAttribute(lstm_rec, cudaFuncAttributeMaxDynamicSharedMemorySize, RSM_TOTAL);
    lstm_rec<<<NBLK, 256, RSM_TOTAL>>>(h0, c0, out);
}